// round 16
// baseline (speedup 1.0000x reference)
#include <cuda_runtime.h>
#include <cuda_fp16.h>
#include <math.h>
#include <stdint.h>

#define B_  8
#define L_  1024
#define S_  512
#define C_  768
#define H_  8
#define D_  96
#define F_  3072
#define NTX (B_*L_)
#define NTC (B_*S_)
#define RS 8

// ---------------- scratch ----------------
__device__ __half g_XN[(size_t)NTX*C_ + 64];
__device__ __half g_CN[(size_t)NTC*C_ + 64];
__device__ __half g_QKV[(size_t)NTX*3*C_ + 64];
__device__ __half g_Qc [(size_t)NTX*C_ + 64];
__device__ __half g_KVc[(size_t)NTC*2*C_ + 64];
__device__ __half g_AO[(size_t)NTX*C_ + 64];
__device__ float  g_X2[(size_t)NTX*C_ + 64];
__device__ __half g_Hh[(size_t)NTX*F_ + 64];
__device__ float  g_VM[(size_t)B_*C_ + 64];
__device__ float  g_RMp[(size_t)B_*RS*C_ + 64];
__device__ __half g_WTh[(size_t)9437184 + 64];

#define WT_Q1   0
#define WT_KV1  589824
#define WT_O1   1769472
#define WT_Q2   2359296
#define WT_KV2  2949120
#define WT_O2   4128768
#define WT_F1   4718592
#define WT_F2   7077888

// ---------------- reductions ----------------
__device__ __forceinline__ float blockReduceSum(float v) {
    __shared__ float sh[32];
    __syncthreads();
    int lane = threadIdx.x & 31, wid = threadIdx.x >> 5;
    #pragma unroll
    for (int o = 16; o; o >>= 1) v += __shfl_down_sync(0xffffffffu, v, o);
    if (lane == 0) sh[wid] = v;
    __syncthreads();
    int nw = blockDim.x >> 5;
    v = (threadIdx.x < nw) ? sh[threadIdx.x] : 0.0f;
    if (wid == 0) {
        #pragma unroll
        for (int o = 16; o; o >>= 1) v += __shfl_down_sync(0xffffffffu, v, o);
        if (lane == 0) sh[0] = v;
    }
    __syncthreads();
    return sh[0];
}

// ---------------- layernorm -> fp16 ----------------
__global__ void ln_kernel(const float* __restrict__ X,
                          const float* __restrict__ g, const float* __restrict__ b,
                          __half* __restrict__ Y) {
    const int row = blockIdx.x, tid = threadIdx.x;
    const float4* x4 = (const float4*)(X + (size_t)row * C_);
    float4 v = make_float4(0.f, 0.f, 0.f, 0.f);
    float s = 0.f, s2 = 0.f;
    if (tid < 192) {
        v = x4[tid];
        s  = v.x + v.y + v.z + v.w;
        s2 = v.x*v.x + v.y*v.y + v.z*v.z + v.w*v.w;
    }
    s  = blockReduceSum(s);
    s2 = blockReduceSum(s2);
    const float mean = s * (1.0f / C_);
    const float var  = s2 * (1.0f / C_) - mean * mean;
    const float inv  = rsqrtf(var + 1e-5f);
    if (tid < 192) {
        const float4 gv = ((const float4*)g)[tid];
        const float4 bv = ((const float4*)b)[tid];
        __half2* yp = (__half2*)(Y + (size_t)row * C_ + tid * 4);
        yp[0] = __floats2half2_rn((v.x - mean) * inv * gv.x + bv.x,
                                  (v.y - mean) * inv * gv.y + bv.y);
        yp[1] = __floats2half2_rn((v.z - mean) * inv * gv.z + bv.z,
                                  (v.w - mean) * inv * gv.w + bv.w);
    }
}

// ---------------- weight transpose + fp16 ----------------
__global__ void transcvt_kernel(const float* __restrict__ W, __half* __restrict__ WTh,
                                int K, int N) {
    __shared__ float t[32][33];
    const int n0 = blockIdx.x * 32, k0 = blockIdx.y * 32;
    const int tx = threadIdx.x, ty = threadIdx.y;
    #pragma unroll
    for (int i = 0; i < 32; i += 8)
        t[ty + i][tx] = W[(size_t)(k0 + ty + i) * N + n0 + tx];
    __syncthreads();
    #pragma unroll
    for (int i = 0; i < 32; i += 8)
        WTh[(size_t)(n0 + ty + i) * K + k0 + tx] = __float2half(t[tx][ty + i]);
}

// ---------------- asm helpers ----------------
__device__ __forceinline__ void cpa16(uint32_t dst, const void* src) {
    asm volatile("cp.async.cg.shared.global [%0], [%1], 16;\n" :: "r"(dst), "l"(src));
}

__device__ __forceinline__ void mma_f16(float* d, const unsigned* a, const unsigned* b) {
    asm volatile(
        "mma.sync.aligned.m16n8k16.row.col.f32.f16.f16.f32 "
        "{%0,%1,%2,%3}, {%4,%5,%6,%7}, {%8,%9}, {%0,%1,%2,%3};"
        : "+f"(d[0]), "+f"(d[1]), "+f"(d[2]), "+f"(d[3])
        : "r"(a[0]), "r"(a[1]), "r"(a[2]), "r"(a[3]), "r"(b[0]), "r"(b[1]));
}

__device__ __forceinline__ void ldmx4t(unsigned* r, uint32_t addr) {
    asm volatile("ldmatrix.sync.aligned.m8n8.x4.trans.shared.b16 {%0,%1,%2,%3}, [%4];"
                 : "=r"(r[0]), "=r"(r[1]), "=r"(r[2]), "=r"(r[3]) : "r"(addr));
}

// ---------------- V-mean via rowmean @ Wv ----------------
__global__ void rowmean1_kernel(const __half* __restrict__ X, float* __restrict__ part, int Lk) {
    const int b = blockIdx.x, s = blockIdx.y, col = threadIdx.x;
    const int rows = Lk / RS;
    const __half* Xb = X + ((size_t)b * Lk + (size_t)s * rows) * C_ + col;
    float sum = 0.f;
    #pragma unroll 4
    for (int j = 0; j < rows; j++) sum += __half2float(Xb[(size_t)j * C_]);
    part[((size_t)b * RS + s) * C_ + col] = sum;
}
__global__ void rowmean2_matvec_kernel(const float* __restrict__ part,
                                       const float* __restrict__ Wv,
                                       float* __restrict__ VM, int Lk) {
    __shared__ float xm[C_];
    const int b = blockIdx.x, n = threadIdx.x;
    float s = 0.f;
    #pragma unroll
    for (int i = 0; i < RS; i++) s += part[((size_t)b * RS + i) * C_ + n];
    xm[n] = s / (float)Lk;
    __syncthreads();
    float acc = 0.f;
    #pragma unroll 8
    for (int k = 0; k < C_; k++) acc = fmaf(xm[k], Wv[(size_t)k * (2*C_) + n], acc);
    VM[(size_t)b * C_ + n] = acc;
}

// ---------------- fp16 flash attention ----------------
#define FQ 128
#define FK 64
#define QLH 104
#define KLH 104
#define VLH 104
#define PLH 72

__global__ __launch_bounds__(256, 2)
void flash_kernel(const __half* __restrict__ Qg, int qStride,
                  const __half* __restrict__ Kg, const __half* __restrict__ Vg, int kvStride,
                  const float* __restrict__ VM, __half* __restrict__ AO,
                  const int* __restrict__ eff, const int* __restrict__ usp,
                  int Lk, int self_mode) {
    extern __shared__ __half hsm[];
    __half* Qs = hsm;
    __half* Ks = Qs + FQ*QLH;
    __half* Vs = Ks + 2*FK*KLH;
    __half* Ps = Vs + 2*FK*VLH;

    const int bh = blockIdx.y, b = bh >> 3, h = bh & 7;
    const int i0 = blockIdx.x * FQ;
    const int e  = eff[b];
    const int el = e * usp[0];
    const int jl = self_mode ? el : e;

    const int tid = threadIdx.x, lane = tid & 31, warp = tid >> 5;
    const int g = lane >> 2, tg = lane & 3;
    const int wm = warp * 16;

    const __half* Qrow = Qg + ((size_t)b * L_ + i0) * qStride + h * D_;
    const __half* Kb   = Kg + (size_t)b * Lk * kvStride + h * D_;
    const __half* Vb   = Vg + (size_t)b * Lk * kvStride + h * D_;
    __half*       AOb  = AO + ((size_t)b * L_ + i0) * C_ + h * D_;

    const int rm0 = (el > i0) ? ((el - i0 < FQ) ? (el - i0) : FQ) : 0;
    if (rm0 < FQ) {
        const float* vm = VM + (size_t)b * C_ + h * D_;
        for (int idx = tid; idx < (FQ - rm0) * D_; idx += 256) {
            int r = rm0 + idx / D_, cc = idx % D_;
            AOb[(size_t)r * C_ + cc] = __float2half(vm[cc]);
        }
    }
    if (rm0 == 0) return;

    {
        const uint32_t sq = (uint32_t)__cvta_generic_to_shared(Qs);
        #pragma unroll
        for (int i = 0; i < 6; i++) {
            int t = tid + i * 256;
            int r = t / 12, sg = (t % 12) * 8;
            cpa16(sq + (uint32_t)((r * QLH + sg) * 2), Qrow + (size_t)r * qStride + sg);
        }
        asm volatile("cp.async.commit_group;\n");
    }

    const uint32_t sk = (uint32_t)__cvta_generic_to_shared(Ks);
    const uint32_t sv = (uint32_t)__cvta_generic_to_shared(Vs);
    const int nkt = (jl + FK - 1) / FK;

    auto load_kv = [&](int t, int buf) {
        const int j0 = t * FK;
        #pragma unroll
        for (int i = 0; i < 3; i++) {
            int c = tid + i * 256;
            int r = c / 12, sg = (c % 12) * 8;
            const size_t off = (size_t)(j0 + r) * kvStride + sg;
            cpa16(sk + (uint32_t)((buf * FK * KLH + r * KLH + sg) * 2), Kb + off);
            cpa16(sv + (uint32_t)((buf * FK * VLH + r * VLH + sg) * 2), Vb + off);
        }
        asm volatile("cp.async.commit_group;\n");
    };

    load_kv(0, 0);
    asm volatile("cp.async.wait_group 0;\n");
    __syncthreads();

    const float scale = rsqrtf((float)D_);
    unsigned qf[6][4];
    #pragma unroll
    for (int kk = 0; kk < 6; kk++) {
        const __half* ap = Qs + (wm + g) * QLH + kk * 16 + 2 * tg;
        qf[kk][0] = *(const unsigned*)ap;
        qf[kk][1] = *(const unsigned*)(ap + 8 * QLH);
        qf[kk][2] = *(const unsigned*)(ap + 8);
        qf[kk][3] = *(const unsigned*)(ap + 8 * QLH + 8);
    }

    float Oacc[12][4] = {};
    float m0 = -1e30f, m1 = -1e30f, l0 = 0.f, l1 = 0.f;

    for (int t = 0; t < nkt; t++) {
        const int buf = t & 1;
        if (t + 1 < nkt) {
            load_kv(t + 1, buf ^ 1);
            asm volatile("cp.async.wait_group 1;\n");
        } else {
            asm volatile("cp.async.wait_group 0;\n");
        }
        __syncthreads();

        const __half* Kst = Ks + buf * FK * KLH;
        const uint32_t svst = sv + (uint32_t)(buf * FK * VLH * 2);

        // ---- S = Q @ K^T ----
        float sacc[8][4] = {};
        #pragma unroll
        for (int kk = 0; kk < 6; kk++) {
            unsigned bf[8][2];
            #pragma unroll
            for (int ni = 0; ni < 8; ni++) {
                const __half* bp = Kst + (ni * 8 + g) * KLH + kk * 16 + 2 * tg;
                bf[ni][0] = *(const unsigned*)bp;
                bf[ni][1] = *(const unsigned*)(bp + 8);
            }
            #pragma unroll
            for (int ni = 0; ni < 8; ni++)
                mma_f16(sacc[ni], qf[kk], bf[ni]);
        }
        #pragma unroll
        for (int ni = 0; ni < 8; ni++) {
            sacc[ni][0] *= scale; sacc[ni][1] *= scale;
            sacc[ni][2] *= scale; sacc[ni][3] *= scale;
        }

        // ---- mask ----
        const int jb = t * FK + 2 * tg;
        #pragma unroll
        for (int ni = 0; ni < 8; ni++) {
            const int j = jb + ni * 8;
            if (j     >= jl) { sacc[ni][0] = -1e30f; sacc[ni][2] = -1e30f; }
            if (j + 1 >= jl) { sacc[ni][1] = -1e30f; sacc[ni][3] = -1e30f; }
        }

        // ---- online softmax ----
        float mx0 = -1e30f, mx1 = -1e30f;
        #pragma unroll
        for (int ni = 0; ni < 8; ni++) {
            mx0 = fmaxf(mx0, fmaxf(sacc[ni][0], sacc[ni][1]));
            mx1 = fmaxf(mx1, fmaxf(sacc[ni][2], sacc[ni][3]));
        }
        mx0 = fmaxf(mx0, __shfl_xor_sync(0xffffffffu, mx0, 1));
        mx0 = fmaxf(mx0, __shfl_xor_sync(0xffffffffu, mx0, 2));
        mx1 = fmaxf(mx1, __shfl_xor_sync(0xffffffffu, mx1, 1));
        mx1 = fmaxf(mx1, __shfl_xor_sync(0xffffffffu, mx1, 2));
        const float nm0 = fmaxf(m0, mx0), nm1 = fmaxf(m1, mx1);
        const float a0 = __expf(m0 - nm0), a1 = __expf(m1 - nm1);
        float rs0 = 0.f, rs1 = 0.f;
        #pragma unroll
        for (int ni = 0; ni < 8; ni++) {
            sacc[ni][0] = __expf(sacc[ni][0] - nm0);
            sacc[ni][1] = __expf(sacc[ni][1] - nm0);
            sacc[ni][2] = __expf(sacc[ni][2] - nm1);
            sacc[ni][3] = __expf(sacc[ni][3] - nm1);
            rs0 += sacc[ni][0] + sacc[ni][1];
            rs1 += sacc[ni][2] + sacc[ni][3];
        }
        rs0 += __shfl_xor_sync(0xffffffffu, rs0, 1);
        rs0 += __shfl_xor_sync(0xffffffffu, rs0, 2);
        rs1 += __shfl_xor_sync(0xffffffffu, rs1, 1);
        rs1 += __shfl_xor_sync(0xffffffffu, rs1, 2);
        l0 = l0 * a0 + rs0;
        l1 = l1 * a1 + rs1;
        m0 = nm0; m1 = nm1;
        #pragma unroll
        for (int nj = 0; nj < 12; nj++) {
            Oacc[nj][0] *= a0; Oacc[nj][1] *= a0;
            Oacc[nj][2] *= a1; Oacc[nj][3] *= a1;
        }

        // ---- stage P fp16 (warp-private rows) ----
        #pragma unroll
        for (int ni = 0; ni < 8; ni++) {
            *(__half2*)&Ps[(wm+g  )*PLH + ni*8 + 2*tg] = __floats2half2_rn(sacc[ni][0], sacc[ni][1]);
            *(__half2*)&Ps[(wm+g+8)*PLH + ni*8 + 2*tg] = __floats2half2_rn(sacc[ni][2], sacc[ni][3]);
        }
        __syncwarp();

        // ---- O += P @ V (V fragments via ldmatrix.trans) ----
        const int vrow = (lane & 7) + (lane & 8);
        const int vcol = (lane & 16) >> 1;
        #pragma unroll
        for (int kk = 0; kk < 4; kk++) {
            unsigned af[4];
            const __half* pp = Ps + (wm + g) * PLH + kk * 16 + 2 * tg;
            af[0] = *(const unsigned*)pp;
            af[1] = *(const unsigned*)(pp + 8 * PLH);
            af[2] = *(const unsigned*)(pp + 8);
            af[3] = *(const unsigned*)(pp + 8 * PLH + 8);
            #pragma unroll
            for (int njp = 0; njp < 6; njp++) {
                unsigned vr[4];
                const uint32_t va = svst +
                    (uint32_t)(((kk * 16 + vrow) * VLH + njp * 16 + vcol) * 2);
                ldmx4t(vr, va);
                mma_f16(Oacc[2*njp    ], af, vr);
                mma_f16(Oacc[2*njp + 1], af, vr + 2);
            }
        }
        __syncthreads();
    }

    const float inv0 = 1.f / l0, inv1 = 1.f / l1;
    #pragma unroll
    for (int nj = 0; nj < 12; nj++) {
        const int ccol = nj*8 + 2*tg;
        if (i0 + wm + g < el)
            *(__half2*)&AOb[(size_t)(wm+g  )*C_ + ccol] =
                __floats2half2_rn(Oacc[nj][0]*inv0, Oacc[nj][1]*inv0);
        if (i0 + wm + g + 8 < el)
            *(__half2*)&AOb[(size_t)(wm+g+8)*C_ + ccol] =
                __floats2half2_rn(Oacc[nj][2]*inv1, Oacc[nj][3]*inv1);
    }
}

// ---------------- fp16 GEMM: 4-stage, single-sync mainloop ----------------
#define HLD 40
#define HSTG (128*HLD)
#define NSTAGE 4
#define HSMEM (NSTAGE * 2 * HSTG * 2)

template <int EPI, int OUTH>
__global__ __launch_bounds__(256, 2)
void h_gemm(const __half* __restrict__ Ah, const __half* __restrict__ WTh,
            const float* __restrict__ bias, const float* __restrict__ R,
            void* __restrict__ Cc,
            int M, int N, int K, int lda, int ldc,
            const int* __restrict__ eff, const int* __restrict__ usp,
            int rowsPB, int multMode) {
    const int m0 = blockIdx.y * 128, n0 = blockIdx.x * 128;
    if (rowsPB) {
        const int b = m0 / rowsPB;
        const int mult = multMode ? usp[0] : 1;
        if (m0 - b * rowsPB >= eff[b] * mult) return;
    }

    extern __shared__ __half hsm[];
    __half* As = hsm;
    __half* Bs = hsm + NSTAGE * HSTG;
    const uint32_t sa = (uint32_t)__cvta_generic_to_shared(As);
    const uint32_t sb = (uint32_t)__cvta_generic_to_shared(Bs);

    const int tid = threadIdx.x, lane = tid & 31, warp = tid >> 5;
    const int wm = (warp & 1) * 64;
    const int wn = (warp >> 1) * 32;
    const int g = lane >> 2, tg = lane & 3;

    float acc[4][4][4] = {};
    const int nIter = K >> 5;

    auto load_tile = [&](int it, int buf) {
        const int kb = it * 32;
        #pragma unroll
        for (int i = 0; i < 2; i++) {
            const int c = tid + i * 256;
            const int row = c >> 2, kc = (c & 3) * 8;
            cpa16(sa + (uint32_t)((buf * HSTG + row * HLD + kc) * 2),
                  Ah + (size_t)(m0 + row) * lda + kb + kc);
        }
        #pragma unroll
        for (int i = 0; i < 2; i++) {
            const int c = tid + i * 256;
            const int row = c >> 2, kc = (c & 3) * 8;
            cpa16(sb + (uint32_t)((buf * HSTG + row * HLD + kc) * 2),
                  WTh + (size_t)(n0 + row) * K + kb + kc);
        }
        asm volatile("cp.async.commit_group;\n");
    };

    // prologue: fill NSTAGE-1 stages
    #pragma unroll
    for (int s = 0; s < NSTAGE - 1; s++)
        if (s < nIter) load_tile(s, s);

    for (int it = 0; it < nIter; it++) {
        // wait until tile `it` is resident (pending newer tiles <= rem)
        const int rem = nIter - 1 - it;
        if (rem >= NSTAGE - 2) {
            asm volatile("cp.async.wait_group %0;\n" :: "n"(NSTAGE - 2));
        } else if (rem == 1) {
            asm volatile("cp.async.wait_group 1;\n");
        } else {
            asm volatile("cp.async.wait_group 0;\n");
        }
        __syncthreads();

        // prefetch tile it+NSTAGE-1 into buffer consumed at it-1 (safe: all
        // threads passed the sync above after finishing it-1)
        if (it + NSTAGE - 1 < nIter)
            load_tile(it + NSTAGE - 1, (it + NSTAGE - 1) % NSTAGE);

        const int buf = it % NSTAGE;
        const __half* Asb = As + buf * HSTG;
        const __half* Bsb = Bs + buf * HSTG;
        #pragma unroll
        for (int kk = 0; kk < 32; kk += 16) {
            unsigned a[4][4], bfr[4][2];
            #pragma unroll
            for (int mi = 0; mi < 4; mi++) {
                const __half* ap = Asb + (wm + mi * 16 + g) * HLD + kk + 2 * tg;
                a[mi][0] = *(const unsigned*)ap;
                a[mi][1] = *(const unsigned*)(ap + 8 * HLD);
                a[mi][2] = *(const unsigned*)(ap + 8);
                a[mi][3] = *(const unsigned*)(ap + 8 * HLD + 8);
            }
            #pragma unroll
            for (int ni = 0; ni < 4; ni++) {
                const __half* bp = Bsb + (wn + ni * 8 + g) * HLD + kk + 2 * tg;
                bfr[ni][0] = *(const unsigned*)bp;
                bfr[ni][1] = *(const unsigned*)(bp + 8);
            }
            #pragma unroll
            for (int mi = 0; mi < 4; mi++)
                #pragma unroll
                for (int ni = 0; ni < 4; ni++)
                    mma_f16(acc[mi][ni], a[mi], bfr[ni]);
        }
        // no trailing __syncthreads: next iteration's wait+sync provides it
    }

    #pragma unroll
    for (int mi = 0; mi < 4; mi++) {
        const int r0 = m0 + wm + mi * 16 + g;
        const int r1 = r0 + 8;
        #pragma unroll
        for (int ni = 0; ni < 4; ni++) {
            const int cc = n0 + wn + ni * 8 + 2 * tg;
            float v00 = acc[mi][ni][0], v01 = acc[mi][ni][1];
            float v10 = acc[mi][ni][2], v11 = acc[mi][ni][3];
            if (EPI >= 2) {
                const float2 bz = *(const float2*)&bias[cc];
                v00 += bz.x; v01 += bz.y; v10 += bz.x; v11 += bz.y;
            }
            if (EPI == 2) {
                v00 = 0.5f * v00 * (1.0f + erff(v00 * 0.70710678118654752f));
                v01 = 0.5f * v01 * (1.0f + erff(v01 * 0.70710678118654752f));
                v10 = 0.5f * v10 * (1.0f + erff(v10 * 0.70710678118654752f));
                v11 = 0.5f * v11 * (1.0f + erff(v11 * 0.70710678118654752f));
            }
            if (EPI == 3) {
                const float2 ra = *(const float2*)&R[(size_t)r0 * ldc + cc];
                const float2 rb = *(const float2*)&R[(size_t)r1 * ldc + cc];
                v00 += ra.x; v01 += ra.y; v10 += rb.x; v11 += rb.y;
            }
            if (OUTH) {
                __half* Ch = (__half*)Cc;
                *(__half2*)&Ch[(size_t)r0 * ldc + cc] = __floats2half2_rn(v00, v01);
                *(__half2*)&Ch[(size_t)r1 * ldc + cc] = __floats2half2_rn(v10, v11);
            } else {
                float* Cf = (float*)Cc;
                *(float2*)&Cf[(size_t)r0 * ldc + cc] = make_float2(v00, v01);
                *(float2*)&Cf[(size_t)r1 * ldc + cc] = make_float2(v10, v11);
            }
        }
    }
}

// ---------------- host helpers ----------------
template <int EPI, int OUTH>
static void launch_hgemm(const __half* Ah, const __half* WTh, const float* bias,
                         const float* R, void* C,
                         int M, int N, int K, int lda, int ldc,
                         const int* eff = nullptr, const int* usp = nullptr,
                         int rowsPB = 0, int multMode = 0) {
    cudaFuncSetAttribute(h_gemm<EPI, OUTH>,
                         cudaFuncAttributeMaxDynamicSharedMemorySize, HSMEM);
    dim3 grid(N / 128, M / 128, 1), blk(256);
    h_gemm<EPI, OUTH><<<grid, blk, HSMEM>>>(Ah, WTh, bias, R, C, M, N, K, lda, ldc,
                                            eff, usp, rowsPB, multMode);
}

static void launch_flash(const __half* Q, int qStride,
                         const __half* Kp, const __half* Vp, int kvStride,
                         const float* VM, __half* AO,
                         const int* eff, const int* usr, int Lk, int self_mode) {
    const int smemBytes = (FQ*QLH + 2*FK*KLH + 2*FK*VLH + FQ*PLH) * 2;
    cudaFuncSetAttribute(flash_kernel,
                         cudaFuncAttributeMaxDynamicSharedMemorySize, smemBytes);
    dim3 grid(L_ / FQ, B_ * H_), blk(256);
    flash_kernel<<<grid, blk, smemBytes>>>(Q, qStride, Kp, Vp, kvStride,
                                           VM, AO, eff, usr, Lk, self_mode);
}

static void launch_transcvt(const float* W, __half* WTh, int K, int N) {
    transcvt_kernel<<<dim3(N / 32, K / 32), dim3(32, 8)>>>(W, WTh, K, N);
}

extern "C" void kernel_launch(void* const* d_in, const int* in_sizes, int n_in,
                              void* d_out, int out_size) {
    const float* x    = (const float*)d_in[0];
    const float* c    = (const float*)d_in[1];
    const int*   eff  = (const int*)  d_in[2];
    const int*   usr  = (const int*)  d_in[3];
    const float* Wq1  = (const float*)d_in[4];
    const float* Wkv1 = (const float*)d_in[5];
    const float* Wo1  = (const float*)d_in[6];
    const float* bo1  = (const float*)d_in[7];
    const float* Wq2  = (const float*)d_in[8];
    const float* Wkv2 = (const float*)d_in[9];
    const float* Wo2  = (const float*)d_in[10];
    const float* bo2  = (const float*)d_in[11];
    const float* g1   = (const float*)d_in[12];
    const float* b1   = (const float*)d_in[13];
    const float* g2   = (const float*)d_in[14];
    const float* b2   = (const float*)d_in[15];
    const float* g4   = (const float*)d_in[16];
    const float* b4   = (const float*)d_in[17];
    const float* gc   = (const float*)d_in[18];
    const float* bc   = (const float*)d_in[19];
    const float* Wf1  = (const float*)d_in[20];
    const float* bf1  = (const float*)d_in[21];
    const float* Wf2  = (const float*)d_in[22];
    const float* bf2  = (const float*)d_in[23];
    float* out = (float*)d_out;

    __half *XN, *CN, *QKV, *Qc, *KVc, *AO, *Hf, *WT;
    float *X2, *VM, *RMp;
    cudaGetSymbolAddress((void**)&XN,  g_XN);
    cudaGetSymbolAddress((void**)&CN,  g_CN);
    cudaGetSymbolAddress((void**)&QKV, g_QKV);
    cudaGetSymbolAddress((void**)&Qc,  g_Qc);
    cudaGetSymbolAddress((void**)&KVc, g_KVc);
    cudaGetSymbolAddress((void**)&AO,  g_AO);
    cudaGetSymbolAddress((void**)&X2,  g_X2);
    cudaGetSymbolAddress((void**)&Hf,  g_Hh);
    cudaGetSymbolAddress((void**)&VM,  g_VM);
    cudaGetSymbolAddress((void**)&RMp, g_RMp);
    cudaGetSymbolAddress((void**)&WT,  g_WTh);

    // ---------- weight transpose + fp16 convert ----------
    launch_transcvt(Wq1,  WT + WT_Q1,  C_, C_);
    launch_transcvt(Wkv1, WT + WT_KV1, C_, 2*C_);
    launch_transcvt(Wo1,  WT + WT_O1,  C_, C_);
    launch_transcvt(Wq2,  WT + WT_Q2,  C_, C_);
    launch_transcvt(Wkv2, WT + WT_KV2, C_, 2*C_);
    launch_transcvt(Wo2,  WT + WT_O2,  C_, C_);
    launch_transcvt(Wf1,  WT + WT_F1,  C_, F_);
    launch_transcvt(Wf2,  WT + WT_F2,  F_, C_);

    // ---------- self-attention (fused QKV projection, N=2304) ----------
    ln_kernel<<<NTX, 256>>>(x, g1, b1, XN);
    launch_hgemm<0,1>(XN, WT + WT_Q1, nullptr, nullptr, QKV, NTX, 3*C_, C_, C_, 3*C_,
                      eff, usr, L_, 1);
    rowmean1_kernel<<<dim3(B_, RS), C_>>>(XN, RMp, L_);
    rowmean2_matvec_kernel<<<B_, C_>>>(RMp, Wkv1 + C_, VM, L_);
    launch_flash(QKV, 3*C_, QKV + C_, QKV + 2*C_, 3*C_, VM, AO, eff, usr, L_, 1);
    launch_hgemm<3,0>(AO, WT + WT_O1, bo1, x, X2, NTX, C_, C_, C_, C_);

    // ---------- cross-attention ----------
    ln_kernel<<<NTX, 256>>>(X2, g2, b2, XN);
    ln_kernel<<<NTC, 256>>>(c,  gc, bc, CN);
    launch_hgemm<0,1>(XN, WT + WT_Q2,  nullptr, nullptr, Qc,  NTX, C_,   C_, C_, C_,
                      eff, usr, L_, 1);
    launch_hgemm<0,1>(CN, WT + WT_KV2, nullptr, nullptr, KVc, NTC, 2*C_, C_, C_, 2*C_,
                      eff, usr, S_, 0);
    rowmean1_kernel<<<dim3(B_, RS), C_>>>(CN, RMp, S_);
    rowmean2_matvec_kernel<<<B_, C_>>>(RMp, Wkv2 + C_, VM, S_);
    launch_flash(Qc, C_, KVc, KVc + C_, 2*C_, VM, AO, eff, usr, S_, 0);
    launch_hgemm<3,0>(AO, WT + WT_O2, bo2, X2, X2, NTX, C_, C_, C_, C_);

    // ---------- FFN ----------
    ln_kernel<<<NTX, 256>>>(X2, g4, b4, XN);
    launch_hgemm<2,1>(XN, WT + WT_F1, bf1, nullptr, Hf, NTX, F_, C_, C_, F_);
    launch_hgemm<3,0>(Hf, WT + WT_F2, bf2, X2, out, NTX, C_, F_, F_, C_);
}

// round 17
// speedup vs baseline: 1.0812x; 1.0812x over previous
#include <cuda_runtime.h>
#include <cuda_fp16.h>
#include <math.h>
#include <stdint.h>

#define B_  8
#define L_  1024
#define S_  512
#define C_  768
#define H_  8
#define D_  96
#define F_  3072
#define NTX (B_*L_)
#define NTC (B_*S_)
#define RS 32

// ---------------- scratch ----------------
__device__ __half g_XN[(size_t)NTX*C_ + 64];
__device__ __half g_CN[(size_t)NTC*C_ + 64];
__device__ __half g_QKV[(size_t)NTX*3*C_ + 64];
__device__ __half g_Qc [(size_t)NTX*C_ + 64];
__device__ __half g_KVc[(size_t)NTC*2*C_ + 64];
__device__ __half g_AO[(size_t)NTX*C_ + 64];
__device__ float  g_X2[(size_t)NTX*C_ + 64];
__device__ __half g_Hh[(size_t)NTX*F_ + 64];
__device__ float  g_VM[(size_t)B_*C_ + 64];
__device__ float  g_RMp[(size_t)B_*RS*C_ + 64];
__device__ __half g_WTh[(size_t)9437184 + 64];

#define WT_Q1   0
#define WT_KV1  589824
#define WT_O1   1769472
#define WT_Q2   2359296
#define WT_KV2  2949120
#define WT_O2   4128768
#define WT_F1   4718592
#define WT_F2   7077888

// ---------------- reductions ----------------
__device__ __forceinline__ float blockReduceSum(float v) {
    __shared__ float sh[32];
    __syncthreads();
    int lane = threadIdx.x & 31, wid = threadIdx.x >> 5;
    #pragma unroll
    for (int o = 16; o; o >>= 1) v += __shfl_down_sync(0xffffffffu, v, o);
    if (lane == 0) sh[wid] = v;
    __syncthreads();
    int nw = blockDim.x >> 5;
    v = (threadIdx.x < nw) ? sh[threadIdx.x] : 0.0f;
    if (wid == 0) {
        #pragma unroll
        for (int o = 16; o; o >>= 1) v += __shfl_down_sync(0xffffffffu, v, o);
        if (lane == 0) sh[0] = v;
    }
    __syncthreads();
    return sh[0];
}

// ---------------- layernorm -> fp16 ----------------
__global__ void ln_kernel(const float* __restrict__ X,
                          const float* __restrict__ g, const float* __restrict__ b,
                          __half* __restrict__ Y) {
    const int row = blockIdx.x, tid = threadIdx.x;
    const float4* x4 = (const float4*)(X + (size_t)row * C_);
    float4 v = make_float4(0.f, 0.f, 0.f, 0.f);
    float s = 0.f, s2 = 0.f;
    if (tid < 192) {
        v = x4[tid];
        s  = v.x + v.y + v.z + v.w;
        s2 = v.x*v.x + v.y*v.y + v.z*v.z + v.w*v.w;
    }
    s  = blockReduceSum(s);
    s2 = blockReduceSum(s2);
    const float mean = s * (1.0f / C_);
    const float var  = s2 * (1.0f / C_) - mean * mean;
    const float inv  = rsqrtf(var + 1e-5f);
    if (tid < 192) {
        const float4 gv = ((const float4*)g)[tid];
        const float4 bv = ((const float4*)b)[tid];
        __half2* yp = (__half2*)(Y + (size_t)row * C_ + tid * 4);
        yp[0] = __floats2half2_rn((v.x - mean) * inv * gv.x + bv.x,
                                  (v.y - mean) * inv * gv.y + bv.y);
        yp[1] = __floats2half2_rn((v.z - mean) * inv * gv.z + bv.z,
                                  (v.w - mean) * inv * gv.w + bv.w);
    }
}

// ---------------- fused weight transpose+convert (all 8 weights, 1 launch) ----------------
struct TcvtArgs {
    const float* W[8];
    long long off[8];
    int K[8], N[8];
    int start[9];
};

__global__ void transcvt_all_kernel(TcvtArgs a, __half* __restrict__ WTh) {
    __shared__ float t[32][33];
    const int bid = blockIdx.x;
    int w = 0;
    #pragma unroll
    for (int i = 1; i < 8; i++) if (bid >= a.start[i]) w = i;
    const int tidx = bid - a.start[w];
    const int tilesN = a.N[w] >> 5;
    const int n0 = (tidx % tilesN) * 32, k0 = (tidx / tilesN) * 32;
    const float* W = a.W[w];
    __half* dst = WTh + a.off[w];
    const int K = a.K[w], N = a.N[w];
    const int tx = threadIdx.x, ty = threadIdx.y;
    #pragma unroll
    for (int i = 0; i < 32; i += 8)
        t[ty + i][tx] = W[(size_t)(k0 + ty + i) * N + n0 + tx];
    __syncthreads();
    #pragma unroll
    for (int i = 0; i < 32; i += 8)
        dst[(size_t)(n0 + ty + i) * K + k0 + tx] = __float2half(t[tx][ty + i]);
}

// ---------------- asm helpers ----------------
__device__ __forceinline__ void cpa16(uint32_t dst, const void* src) {
    asm volatile("cp.async.cg.shared.global [%0], [%1], 16;\n" :: "r"(dst), "l"(src));
}

__device__ __forceinline__ void mma_f16(float* d, const unsigned* a, const unsigned* b) {
    asm volatile(
        "mma.sync.aligned.m16n8k16.row.col.f32.f16.f16.f32 "
        "{%0,%1,%2,%3}, {%4,%5,%6,%7}, {%8,%9}, {%0,%1,%2,%3};"
        : "+f"(d[0]), "+f"(d[1]), "+f"(d[2]), "+f"(d[3])
        : "r"(a[0]), "r"(a[1]), "r"(a[2]), "r"(a[3]), "r"(b[0]), "r"(b[1]));
}

__device__ __forceinline__ void ldmx4(unsigned* r, uint32_t addr) {
    asm volatile("ldmatrix.sync.aligned.m8n8.x4.shared.b16 {%0,%1,%2,%3}, [%4];"
                 : "=r"(r[0]), "=r"(r[1]), "=r"(r[2]), "=r"(r[3]) : "r"(addr));
}

__device__ __forceinline__ void ldmx4t(unsigned* r, uint32_t addr) {
    asm volatile("ldmatrix.sync.aligned.m8n8.x4.trans.shared.b16 {%0,%1,%2,%3}, [%4];"
                 : "=r"(r[0]), "=r"(r[1]), "=r"(r[2]), "=r"(r[3]) : "r"(addr));
}

// ---------------- V-mean via rowmean @ Wv ----------------
// phase1: grid (B, RS), block 384: __half2 column partial sums
__global__ void rowmean1_kernel(const __half* __restrict__ X, float* __restrict__ part, int Lk) {
    const int b = blockIdx.x, s = blockIdx.y, col = threadIdx.x * 2;
    const int rows = Lk / RS;
    const __half* Xb = X + ((size_t)b * Lk + (size_t)s * rows) * C_ + col;
    float s0 = 0.f, s1 = 0.f;
    #pragma unroll 4
    for (int j = 0; j < rows; j++) {
        const __half2 h = *(const __half2*)(Xb + (size_t)j * C_);
        const float2 f = __half22float2(h);
        s0 += f.x; s1 += f.y;
    }
    float* p = part + ((size_t)b * RS + s) * C_ + col;
    p[0] = s0; p[1] = s1;
}
__global__ void rowmean2_matvec_kernel(const float* __restrict__ part,
                                       const float* __restrict__ Wv,
                                       float* __restrict__ VM, int Lk) {
    __shared__ float xm[C_];
    const int b = blockIdx.x, n = threadIdx.x;
    float s = 0.f;
    #pragma unroll
    for (int i = 0; i < RS; i++) s += part[((size_t)b * RS + i) * C_ + n];
    xm[n] = s / (float)Lk;
    __syncthreads();
    float acc = 0.f;
    #pragma unroll 8
    for (int k = 0; k < C_; k++) acc = fmaf(xm[k], Wv[(size_t)k * (2*C_) + n], acc);
    VM[(size_t)b * C_ + n] = acc;
}

// ---------------- fp16 flash attention ----------------
#define FQ 128
#define FK 64
#define QLH 104
#define KLH 104
#define VLH 104
#define PLH 72

__global__ __launch_bounds__(256, 2)
void flash_kernel(const __half* __restrict__ Qg, int qStride,
                  const __half* __restrict__ Kg, const __half* __restrict__ Vg, int kvStride,
                  const float* __restrict__ VM, __half* __restrict__ AO,
                  const int* __restrict__ eff, const int* __restrict__ usp,
                  int Lk, int self_mode) {
    extern __shared__ __half hsm[];
    __half* Qs = hsm;
    __half* Ks = Qs + FQ*QLH;
    __half* Vs = Ks + 2*FK*KLH;
    __half* Ps = Vs + 2*FK*VLH;

    const int bh = blockIdx.y, b = bh >> 3, h = bh & 7;
    const int i0 = blockIdx.x * FQ;
    const int e  = eff[b];
    const int el = e * usp[0];
    const int jl = self_mode ? el : e;

    const int tid = threadIdx.x, lane = tid & 31, warp = tid >> 5;
    const int g = lane >> 2, tg = lane & 3;
    const int wm = warp * 16;

    const __half* Qrow = Qg + ((size_t)b * L_ + i0) * qStride + h * D_;
    const __half* Kb   = Kg + (size_t)b * Lk * kvStride + h * D_;
    const __half* Vb   = Vg + (size_t)b * Lk * kvStride + h * D_;
    __half*       AOb  = AO + ((size_t)b * L_ + i0) * C_ + h * D_;

    const int rm0 = (el > i0) ? ((el - i0 < FQ) ? (el - i0) : FQ) : 0;
    if (rm0 < FQ) {
        const float* vm = VM + (size_t)b * C_ + h * D_;
        for (int idx = tid; idx < (FQ - rm0) * D_; idx += 256) {
            int r = rm0 + idx / D_, cc = idx % D_;
            AOb[(size_t)r * C_ + cc] = __float2half(vm[cc]);
        }
    }
    if (rm0 == 0) return;

    {
        const uint32_t sq = (uint32_t)__cvta_generic_to_shared(Qs);
        #pragma unroll
        for (int i = 0; i < 6; i++) {
            int t = tid + i * 256;
            int r = t / 12, sg = (t % 12) * 8;
            cpa16(sq + (uint32_t)((r * QLH + sg) * 2), Qrow + (size_t)r * qStride + sg);
        }
        asm volatile("cp.async.commit_group;\n");
    }

    const uint32_t sk = (uint32_t)__cvta_generic_to_shared(Ks);
    const uint32_t sv = (uint32_t)__cvta_generic_to_shared(Vs);
    const uint32_t sp = (uint32_t)__cvta_generic_to_shared(Ps);
    const int nkt = (jl + FK - 1) / FK;

    auto load_kv = [&](int t, int buf) {
        const int j0 = t * FK;
        #pragma unroll
        for (int i = 0; i < 3; i++) {
            int c = tid + i * 256;
            int r = c / 12, sg = (c % 12) * 8;
            const size_t off = (size_t)(j0 + r) * kvStride + sg;
            cpa16(sk + (uint32_t)((buf * FK * KLH + r * KLH + sg) * 2), Kb + off);
            cpa16(sv + (uint32_t)((buf * FK * VLH + r * VLH + sg) * 2), Vb + off);
        }
        asm volatile("cp.async.commit_group;\n");
    };

    load_kv(0, 0);
    asm volatile("cp.async.wait_group 0;\n");
    __syncthreads();

    const float scale = rsqrtf((float)D_);
    unsigned qf[6][4];
    #pragma unroll
    for (int kk = 0; kk < 6; kk++) {
        const __half* ap = Qs + (wm + g) * QLH + kk * 16 + 2 * tg;
        qf[kk][0] = *(const unsigned*)ap;
        qf[kk][1] = *(const unsigned*)(ap + 8 * QLH);
        qf[kk][2] = *(const unsigned*)(ap + 8);
        qf[kk][3] = *(const unsigned*)(ap + 8 * QLH + 8);
    }

    // ldmatrix lane geometry
    const int lrow = lane & 7;
    const int lq   = lane >> 3;              // matrix index 0..3

    float Oacc[12][4] = {};
    float m0 = -1e30f, m1 = -1e30f, l0 = 0.f, l1 = 0.f;

    for (int t = 0; t < nkt; t++) {
        const int buf = t & 1;
        if (t + 1 < nkt) {
            load_kv(t + 1, buf ^ 1);
            asm volatile("cp.async.wait_group 1;\n");
        } else {
            asm volatile("cp.async.wait_group 0;\n");
        }
        __syncthreads();

        const uint32_t skst = sk + (uint32_t)(buf * FK * KLH * 2);
        const uint32_t svst = sv + (uint32_t)(buf * FK * VLH * 2);

        // ---- S = Q @ K^T (K frags via ldmatrix.x4: m-pairs (ni, k-half)) ----
        float sacc[8][4] = {};
        #pragma unroll
        for (int kk = 0; kk < 6; kk++) {
            unsigned bf[8][2];
            #pragma unroll
            for (int nip = 0; nip < 4; nip++) {
                unsigned tr[4];
                const uint32_t ka = skst + (uint32_t)(
                    ((nip * 16 + ((lq >> 1) << 3) + lrow) * KLH
                     + kk * 16 + ((lq & 1) << 3)) * 2);
                ldmx4(tr, ka);
                bf[2*nip  ][0] = tr[0]; bf[2*nip  ][1] = tr[1];
                bf[2*nip+1][0] = tr[2]; bf[2*nip+1][1] = tr[3];
            }
            #pragma unroll
            for (int ni = 0; ni < 8; ni++)
                mma_f16(sacc[ni], qf[kk], bf[ni]);
        }
        #pragma unroll
        for (int ni = 0; ni < 8; ni++) {
            sacc[ni][0] *= scale; sacc[ni][1] *= scale;
            sacc[ni][2] *= scale; sacc[ni][3] *= scale;
        }

        // ---- mask ----
        const int jb = t * FK + 2 * tg;
        #pragma unroll
        for (int ni = 0; ni < 8; ni++) {
            const int j = jb + ni * 8;
            if (j     >= jl) { sacc[ni][0] = -1e30f; sacc[ni][2] = -1e30f; }
            if (j + 1 >= jl) { sacc[ni][1] = -1e30f; sacc[ni][3] = -1e30f; }
        }

        // ---- online softmax ----
        float mx0 = -1e30f, mx1 = -1e30f;
        #pragma unroll
        for (int ni = 0; ni < 8; ni++) {
            mx0 = fmaxf(mx0, fmaxf(sacc[ni][0], sacc[ni][1]));
            mx1 = fmaxf(mx1, fmaxf(sacc[ni][2], sacc[ni][3]));
        }
        mx0 = fmaxf(mx0, __shfl_xor_sync(0xffffffffu, mx0, 1));
        mx0 = fmaxf(mx0, __shfl_xor_sync(0xffffffffu, mx0, 2));
        mx1 = fmaxf(mx1, __shfl_xor_sync(0xffffffffu, mx1, 1));
        mx1 = fmaxf(mx1, __shfl_xor_sync(0xffffffffu, mx1, 2));
        const float nm0 = fmaxf(m0, mx0), nm1 = fmaxf(m1, mx1);
        const float a0 = __expf(m0 - nm0), a1 = __expf(m1 - nm1);
        float rs0 = 0.f, rs1 = 0.f;
        #pragma unroll
        for (int ni = 0; ni < 8; ni++) {
            sacc[ni][0] = __expf(sacc[ni][0] - nm0);
            sacc[ni][1] = __expf(sacc[ni][1] - nm0);
            sacc[ni][2] = __expf(sacc[ni][2] - nm1);
            sacc[ni][3] = __expf(sacc[ni][3] - nm1);
            rs0 += sacc[ni][0] + sacc[ni][1];
            rs1 += sacc[ni][2] + sacc[ni][3];
        }
        rs0 += __shfl_xor_sync(0xffffffffu, rs0, 1);
        rs0 += __shfl_xor_sync(0xffffffffu, rs0, 2);
        rs1 += __shfl_xor_sync(0xffffffffu, rs1, 1);
        rs1 += __shfl_xor_sync(0xffffffffu, rs1, 2);
        l0 = l0 * a0 + rs0;
        l1 = l1 * a1 + rs1;
        m0 = nm0; m1 = nm1;
        #pragma unroll
        for (int nj = 0; nj < 12; nj++) {
            Oacc[nj][0] *= a0; Oacc[nj][1] *= a0;
            Oacc[nj][2] *= a1; Oacc[nj][3] *= a1;
        }

        // ---- stage P fp16 (warp-private rows) ----
        #pragma unroll
        for (int ni = 0; ni < 8; ni++) {
            *(__half2*)&Ps[(wm+g  )*PLH + ni*8 + 2*tg] = __floats2half2_rn(sacc[ni][0], sacc[ni][1]);
            *(__half2*)&Ps[(wm+g+8)*PLH + ni*8 + 2*tg] = __floats2half2_rn(sacc[ni][2], sacc[ni][3]);
        }
        __syncwarp();

        // ---- O += P @ V (P frags via ldmatrix, V frags via ldmatrix.trans) ----
        const int vrow = (lane & 7) + (lane & 8);
        const int vcol = (lane & 16) >> 1;
        #pragma unroll
        for (int kk = 0; kk < 4; kk++) {
            unsigned af[4];
            const uint32_t pa = sp + (uint32_t)(
                ((wm + ((lq & 1) << 3) + lrow) * PLH + kk * 16 + ((lq >> 1) << 3)) * 2);
            ldmx4(af, pa);
            #pragma unroll
            for (int njp = 0; njp < 6; njp++) {
                unsigned vr[4];
                const uint32_t va = svst +
                    (uint32_t)(((kk * 16 + vrow) * VLH + njp * 16 + vcol) * 2);
                ldmx4t(vr, va);
                mma_f16(Oacc[2*njp    ], af, vr);
                mma_f16(Oacc[2*njp + 1], af, vr + 2);
            }
        }
        __syncthreads();
    }

    const float inv0 = 1.f / l0, inv1 = 1.f / l1;
    #pragma unroll
    for (int nj = 0; nj < 12; nj++) {
        const int ccol = nj*8 + 2*tg;
        if (i0 + wm + g < el)
            *(__half2*)&AOb[(size_t)(wm+g  )*C_ + ccol] =
                __floats2half2_rn(Oacc[nj][0]*inv0, Oacc[nj][1]*inv0);
        if (i0 + wm + g + 8 < el)
            *(__half2*)&AOb[(size_t)(wm+g+8)*C_ + ccol] =
                __floats2half2_rn(Oacc[nj][2]*inv1, Oacc[nj][3]*inv1);
    }
}

// ---------------- fp16 GEMM with ldmatrix fragment loads ----------------
#define HLD 40
#define HSTG (128*HLD)
#define NSTAGE 3
#define HSMEM (NSTAGE * 2 * HSTG * 2)

template <int EPI, int OUTH>
__global__ __launch_bounds__(256, 2)
void h_gemm(const __half* __restrict__ Ah, const __half* __restrict__ WTh,
            const float* __restrict__ bias, const float* __restrict__ R,
            void* __restrict__ Cc,
            int M, int N, int K, int lda, int ldc,
            const int* __restrict__ eff, const int* __restrict__ usp,
            int rowsPB, int multMode) {
    const int m0 = blockIdx.y * 128, n0 = blockIdx.x * 128;
    if (rowsPB) {
        const int b = m0 / rowsPB;
        const int mult = multMode ? usp[0] : 1;
        if (m0 - b * rowsPB >= eff[b] * mult) return;
    }

    extern __shared__ __half hsm[];
    __half* As = hsm;
    __half* Bs = hsm + NSTAGE * HSTG;
    const uint32_t sa = (uint32_t)__cvta_generic_to_shared(As);
    const uint32_t sb = (uint32_t)__cvta_generic_to_shared(Bs);

    const int tid = threadIdx.x, lane = tid & 31, warp = tid >> 5;
    const int wm = (warp & 1) * 64;
    const int wn = (warp >> 1) * 32;
    const int g = lane >> 2, tg = lane & 3;
    const int lrow = lane & 7, lq = lane >> 3;

    float acc[4][4][4] = {};
    const int nIter = K >> 5;

    auto load_tile = [&](int it, int buf) {
        const int kb = it * 32;
        #pragma unroll
        for (int i = 0; i < 2; i++) {
            const int c = tid + i * 256;
            const int row = c >> 2, kc = (c & 3) * 8;
            cpa16(sa + (uint32_t)((buf * HSTG + row * HLD + kc) * 2),
                  Ah + (size_t)(m0 + row) * lda + kb + kc);
        }
        #pragma unroll
        for (int i = 0; i < 2; i++) {
            const int c = tid + i * 256;
            const int row = c >> 2, kc = (c & 3) * 8;
            cpa16(sb + (uint32_t)((buf * HSTG + row * HLD + kc) * 2),
                  WTh + (size_t)(n0 + row) * K + kb + kc);
        }
        asm volatile("cp.async.commit_group;\n");
    };

    load_tile(0, 0);
    if (nIter > 1) load_tile(1, 1);

    for (int it = 0; it < nIter; it++) {
        const int buf = it % NSTAGE;
        if (it + 2 < nIter) {
            load_tile(it + 2, (it + 2) % NSTAGE);
            asm volatile("cp.async.wait_group 2;\n");
        } else if (it + 1 < nIter) {
            asm volatile("cp.async.wait_group 1;\n");
        } else {
            asm volatile("cp.async.wait_group 0;\n");
        }
        __syncthreads();

        const uint32_t sab = sa + (uint32_t)(buf * HSTG * 2);
        const uint32_t sbb = sb + (uint32_t)(buf * HSTG * 2);
        #pragma unroll
        for (int kk = 0; kk < 32; kk += 16) {
            unsigned a[4][4], bfr[4][2];
            #pragma unroll
            for (int mi = 0; mi < 4; mi++) {
                const uint32_t aa = sab + (uint32_t)(
                    ((wm + mi * 16 + ((lq & 1) << 3) + lrow) * HLD
                     + kk + ((lq >> 1) << 3)) * 2);
                ldmx4(a[mi], aa);
            }
            #pragma unroll
            for (int nip = 0; nip < 2; nip++) {
                unsigned tr[4];
                const uint32_t ba = sbb + (uint32_t)(
                    ((wn + nip * 16 + ((lq >> 1) << 3) + lrow) * HLD
                     + kk + ((lq & 1) << 3)) * 2);
                ldmx4(tr, ba);
                bfr[2*nip  ][0] = tr[0]; bfr[2*nip  ][1] = tr[1];
                bfr[2*nip+1][0] = tr[2]; bfr[2*nip+1][1] = tr[3];
            }
            #pragma unroll
            for (int mi = 0; mi < 4; mi++)
                #pragma unroll
                for (int ni = 0; ni < 4; ni++)
                    mma_f16(acc[mi][ni], a[mi], bfr[ni]);
        }
        __syncthreads();
    }

    #pragma unroll
    for (int mi = 0; mi < 4; mi++) {
        const int r0 = m0 + wm + mi * 16 + g;
        const int r1 = r0 + 8;
        #pragma unroll
        for (int ni = 0; ni < 4; ni++) {
            const int cc = n0 + wn + ni * 8 + 2 * tg;
            float v00 = acc[mi][ni][0], v01 = acc[mi][ni][1];
            float v10 = acc[mi][ni][2], v11 = acc[mi][ni][3];
            if (EPI >= 2) {
                const float2 bz = *(const float2*)&bias[cc];
                v00 += bz.x; v01 += bz.y; v10 += bz.x; v11 += bz.y;
            }
            if (EPI == 2) {
                v00 = 0.5f * v00 * (1.0f + erff(v00 * 0.70710678118654752f));
                v01 = 0.5f * v01 * (1.0f + erff(v01 * 0.70710678118654752f));
                v10 = 0.5f * v10 * (1.0f + erff(v10 * 0.70710678118654752f));
                v11 = 0.5f * v11 * (1.0f + erff(v11 * 0.70710678118654752f));
            }
            if (EPI == 3) {
                const float2 ra = *(const float2*)&R[(size_t)r0 * ldc + cc];
                const float2 rb = *(const float2*)&R[(size_t)r1 * ldc + cc];
                v00 += ra.x; v01 += ra.y; v10 += rb.x; v11 += rb.y;
            }
            if (OUTH) {
                __half* Ch = (__half*)Cc;
                *(__half2*)&Ch[(size_t)r0 * ldc + cc] = __floats2half2_rn(v00, v01);
                *(__half2*)&Ch[(size_t)r1 * ldc + cc] = __floats2half2_rn(v10, v11);
            } else {
                float* Cf = (float*)Cc;
                *(float2*)&Cf[(size_t)r0 * ldc + cc] = make_float2(v00, v01);
                *(float2*)&Cf[(size_t)r1 * ldc + cc] = make_float2(v10, v11);
            }
        }
    }
}

// ---------------- host helpers ----------------
template <int EPI, int OUTH>
static void launch_hgemm(const __half* Ah, const __half* WTh, const float* bias,
                         const float* R, void* C,
                         int M, int N, int K, int lda, int ldc,
                         const int* eff = nullptr, const int* usp = nullptr,
                         int rowsPB = 0, int multMode = 0) {
    cudaFuncSetAttribute(h_gemm<EPI, OUTH>,
                         cudaFuncAttributeMaxDynamicSharedMemorySize, HSMEM);
    dim3 grid(N / 128, M / 128, 1), blk(256);
    h_gemm<EPI, OUTH><<<grid, blk, HSMEM>>>(Ah, WTh, bias, R, C, M, N, K, lda, ldc,
                                            eff, usp, rowsPB, multMode);
}

static void launch_flash(const __half* Q, int qStride,
                         const __half* Kp, const __half* Vp, int kvStride,
                         const float* VM, __half* AO,
                         const int* eff, const int* usr, int Lk, int self_mode) {
    const int smemBytes = (FQ*QLH + 2*FK*KLH + 2*FK*VLH + FQ*PLH) * 2;
    cudaFuncSetAttribute(flash_kernel,
                         cudaFuncAttributeMaxDynamicSharedMemorySize, smemBytes);
    dim3 grid(L_ / FQ, B_ * H_), blk(256);
    flash_kernel<<<grid, blk, smemBytes>>>(Q, qStride, Kp, Vp, kvStride,
                                           VM, AO, eff, usr, Lk, self_mode);
}

extern "C" void kernel_launch(void* const* d_in, const int* in_sizes, int n_in,
                              void* d_out, int out_size) {
    const float* x    = (const float*)d_in[0];
    const float* c    = (const float*)d_in[1];
    const int*   eff  = (const int*)  d_in[2];
    const int*   usr  = (const int*)  d_in[3];
    const float* Wq1  = (const float*)d_in[4];
    const float* Wkv1 = (const float*)d_in[5];
    const float* Wo1  = (const float*)d_in[6];
    const float* bo1  = (const float*)d_in[7];
    const float* Wq2  = (const float*)d_in[8];
    const float* Wkv2 = (const float*)d_in[9];
    const float* Wo2  = (const float*)d_in[10];
    const float* bo2  = (const float*)d_in[11];
    const float* g1   = (const float*)d_in[12];
    const float* b1   = (const float*)d_in[13];
    const float* g2   = (const float*)d_in[14];
    const float* b2   = (const float*)d_in[15];
    const float* g4   = (const float*)d_in[16];
    const float* b4   = (const float*)d_in[17];
    const float* gc   = (const float*)d_in[18];
    const float* bc   = (const float*)d_in[19];
    const float* Wf1  = (const float*)d_in[20];
    const float* bf1  = (const float*)d_in[21];
    const float* Wf2  = (const float*)d_in[22];
    const float* bf2  = (const float*)d_in[23];
    float* out = (float*)d_out;

    __half *XN, *CN, *QKV, *Qc, *KVc, *AO, *Hf, *WT;
    float *X2, *VM, *RMp;
    cudaGetSymbolAddress((void**)&XN,  g_XN);
    cudaGetSymbolAddress((void**)&CN,  g_CN);
    cudaGetSymbolAddress((void**)&QKV, g_QKV);
    cudaGetSymbolAddress((void**)&Qc,  g_Qc);
    cudaGetSymbolAddress((void**)&KVc, g_KVc);
    cudaGetSymbolAddress((void**)&AO,  g_AO);
    cudaGetSymbolAddress((void**)&X2,  g_X2);
    cudaGetSymbolAddress((void**)&Hf,  g_Hh);
    cudaGetSymbolAddress((void**)&VM,  g_VM);
    cudaGetSymbolAddress((void**)&RMp, g_RMp);
    cudaGetSymbolAddress((void**)&WT,  g_WTh);

    // ---------- fused weight transpose + fp16 convert (1 launch) ----------
    {
        TcvtArgs ta;
        const float* Ws[8] = {Wq1, Wkv1, Wo1, Wq2, Wkv2, Wo2, Wf1, Wf2};
        const long long off[8] = {WT_Q1, WT_KV1, WT_O1, WT_Q2, WT_KV2, WT_O2, WT_F1, WT_F2};
        const int Ks[8] = {C_, C_, C_, C_, C_, C_, C_, F_};
        const int Ns[8] = {C_, 2*C_, C_, C_, 2*C_, C_, F_, C_};
        int cum = 0;
        for (int i = 0; i < 8; i++) {
            ta.W[i] = Ws[i]; ta.off[i] = off[i]; ta.K[i] = Ks[i]; ta.N[i] = Ns[i];
            ta.start[i] = cum;
            cum += (Ks[i] / 32) * (Ns[i] / 32);
        }
        ta.start[8] = cum;
        transcvt_all_kernel<<<cum, dim3(32, 8)>>>(ta, WT);
    }

    // ---------- self-attention (fused QKV projection, N=2304) ----------
    ln_kernel<<<NTX, 256>>>(x, g1, b1, XN);
    launch_hgemm<0,1>(XN, WT + WT_Q1, nullptr, nullptr, QKV, NTX, 3*C_, C_, C_, 3*C_,
                      eff, usr, L_, 1);
    rowmean1_kernel<<<dim3(B_, RS), 384>>>(XN, RMp, L_);
    rowmean2_matvec_kernel<<<B_, C_>>>(RMp, Wkv1 + C_, VM, L_);
    launch_flash(QKV, 3*C_, QKV + C_, QKV + 2*C_, 3*C_, VM, AO, eff, usr, L_, 1);
    launch_hgemm<3,0>(AO, WT + WT_O1, bo1, x, X2, NTX, C_, C_, C_, C_);

    // ---------- cross-attention ----------
    ln_kernel<<<NTX, 256>>>(X2, g2, b2, XN);
    ln_kernel<<<NTC, 256>>>(c,  gc, bc, CN);
    launch_hgemm<0,1>(XN, WT + WT_Q2,  nullptr, nullptr, Qc,  NTX, C_,   C_, C_, C_,
                      eff, usr, L_, 1);
    launch_hgemm<0,1>(CN, WT + WT_KV2, nullptr, nullptr, KVc, NTC, 2*C_, C_, C_, 2*C_,
                      eff, usr, S_, 0);
    rowmean1_kernel<<<dim3(B_, RS), 384>>>(CN, RMp, S_);
    rowmean2_matvec_kernel<<<B_, C_>>>(RMp, Wkv2 + C_, VM, S_);
    launch_flash(Qc, C_, KVc, KVc + C_, 2*C_, VM, AO, eff, usr, S_, 0);
    launch_hgemm<3,0>(AO, WT + WT_O2, bo2, X2, X2, NTX, C_, C_, C_, C_);

    // ---------- FFN ----------
    ln_kernel<<<NTX, 256>>>(X2, g4, b4, XN);
    launch_hgemm<2,1>(XN, WT + WT_F1, bf1, nullptr, Hf, NTX, F_, C_, C_, F_);
    launch_hgemm<3,0>(Hf, WT + WT_F2, bf2, X2, out, NTX, C_, F_, F_, C_);
}